// round 10
// baseline (speedup 1.0000x reference)
#include <cuda_runtime.h>
#include <cuda_bf16.h>
#include <cstdint>

#define K_STENCIL 27
#define CIN 32
#define COUT 64
#define M_BLK 192
#define TPB 192
#define BN_EPS 1e-5f
#define MAX_N 320000

// smem row pitch: 64 data bytes + 16 pad -> ldmatrix/STS phases land on
// 8 distinct 16B banks (5*r mod 8 is a permutation of 0..7).
#define APITCH 80
#define A_LO (M_BLK * APITCH + 64)   // lo region offset (+64 = 4-bank shift)
#define B_LO (COUT * APITCH + 64)

// ---------------- device scratch (no allocation allowed) ----------------
__device__ int   g_is64;
__device__ float g_sum[COUT];
__device__ float g_sumsq[COUT];
__device__ float g_scale[COUT];
__device__ float g_bias[COUT];
// packed rows: 32 bf16 hi then 32 bf16 lo = 128 B per node / per (k,cout) row
__device__ __nv_bfloat16 g_data_pk[MAX_N * 64];
__device__ __nv_bfloat16 g_w_pk[K_STENCIL * COUT * 64];
__device__ int g_neigh_t[K_STENCIL * MAX_N];     // [k][node]

__device__ __forceinline__ uint32_t smem_u32(const void* p) {
    uint32_t a;
    asm("{ .reg .u64 t; cvta.to.shared.u64 t, %1; cvt.u32.u64 %0, t; }"
        : "=r"(a) : "l"(p));
    return a;
}

#define LDMATRIX_X4(r0, r1, r2, r3, addr) \
    asm volatile("ldmatrix.sync.aligned.m8n8.x4.shared.b16 {%0,%1,%2,%3}, [%4];" \
        : "=r"(r0), "=r"(r1), "=r"(r2), "=r"(r3) : "r"(addr))

#define MMA_BF16(d, a0, a1, a2, a3, b0, b1) \
    asm volatile("mma.sync.aligned.m16n8k16.row.col.f32.bf16.bf16.f32 " \
        "{%0,%1,%2,%3}, {%4,%5,%6,%7}, {%8,%9}, {%0,%1,%2,%3};" \
        : "+f"((d)[0]), "+f"((d)[1]), "+f"((d)[2]), "+f"((d)[3]) \
        : "r"(a0), "r"(a1), "r"(a2), "r"(a3), "r"(b0), "r"(b1))

// ---------------- small kernels ----------------
__global__ void prep_kernel(const int* __restrict__ neigh_words, int nelems) {
    int t = threadIdx.x;
    if (t < COUT) { g_sum[t] = 0.f; g_sumsq[t] = 0.f; }
    if (t >= 64 && t < 96) {
        int lane = t - 64;
        int v = 0;
        int limit = nelems < 4096 ? nelems : 4096;
        for (int i = 2 * lane + 1; i < limit; i += 64) v |= neigh_words[i];
        v = __reduce_or_sync(0xffffffffu, v);
        if (lane == 0) g_is64 = (v == 0) ? 1 : 0;
    }
}

// neigh [n][k] (int32 or int64) -> g_neigh_t [k][n] int32
__global__ void tneigh_kernel(const void* __restrict__ neigh, int N) {
    int i = blockIdx.x * blockDim.x + threadIdx.x;
    int total = N * K_STENCIL;
    if (i < total) {
        int n = i / K_STENCIL, k = i - n * K_STENCIL;
        long long idx = g_is64 ? ((const long long*)neigh)[i]
                               : (long long)((const int*)neigh)[i];
        g_neigh_t[k * N + n] = (idx >= 0) ? (int)idx : -1;
    }
}

__global__ void cvt_data_kernel(const float* __restrict__ data, int total4) {
    int i = blockIdx.x * blockDim.x + threadIdx.x;
    int stride = gridDim.x * blockDim.x;
    for (; i < total4; i += stride) {
        float4 x = ((const float4*)data)[i];
        int n = i >> 3, c = (i & 7) * 4;
        __nv_bfloat16 h0 = __float2bfloat16_rn(x.x);
        __nv_bfloat16 h1 = __float2bfloat16_rn(x.y);
        __nv_bfloat16 h2 = __float2bfloat16_rn(x.z);
        __nv_bfloat16 h3 = __float2bfloat16_rn(x.w);
        __nv_bfloat16 l0 = __float2bfloat16_rn(x.x - __bfloat162float(h0));
        __nv_bfloat16 l1 = __float2bfloat16_rn(x.y - __bfloat162float(h1));
        __nv_bfloat16 l2 = __float2bfloat16_rn(x.z - __bfloat162float(h2));
        __nv_bfloat16 l3 = __float2bfloat16_rn(x.w - __bfloat162float(h3));
        uint2 hp, lp;
        hp.x = ((uint32_t)__bfloat16_as_ushort(h1) << 16) | __bfloat16_as_ushort(h0);
        hp.y = ((uint32_t)__bfloat16_as_ushort(h3) << 16) | __bfloat16_as_ushort(h2);
        lp.x = ((uint32_t)__bfloat16_as_ushort(l1) << 16) | __bfloat16_as_ushort(l0);
        lp.y = ((uint32_t)__bfloat16_as_ushort(l3) << 16) | __bfloat16_as_ushort(l2);
        *(uint2*)&g_data_pk[n * 64 + c]      = hp;
        *(uint2*)&g_data_pk[n * 64 + 32 + c] = lp;
    }
}

__global__ void cvt_weight_kernel(const float* __restrict__ weight) {
    int i = blockIdx.x * blockDim.x + threadIdx.x;
    int total = K_STENCIL * COUT * CIN;
    if (i < total) {
        int k = i / (COUT * CIN);
        int r = i - k * (COUT * CIN);
        int n = r >> 5;            // cout
        int c = r & 31;            // cin
        float x = weight[(k * CIN + c) * COUT + n];
        __nv_bfloat16 h = __float2bfloat16_rn(x);
        __nv_bfloat16 l = __float2bfloat16_rn(x - __bfloat162float(h));
        g_w_pk[(k * COUT + n) * 64 + c]      = h;
        g_w_pk[(k * COUT + n) * 64 + 32 + c] = l;
    }
}

// ---------------- main conv kernel: warp-level bf16 HMMA, hi/lo split ----
// Block: 192 nodes x 64 couts, 6 warps; warp wm owns nodes [wm*32, wm*32+32)
// as two m16 tiles. Per stencil k: gather 192 packed rows + W_k into smem,
// then each warp runs 2 cs x 4 ntp x 2 mt x 3 combos x (n8 pair) = 96 MMA.
__global__ void __launch_bounds__(TPB, 2) conv_kernel(float* __restrict__ out, int N)
{
    __shared__ __align__(128) char sA[2 * M_BLK * APITCH + 64];  // hi | pad | lo
    __shared__ __align__(128) char sB[2 * COUT * APITCH + 64];
    __shared__ float rsum[COUT], rsq[COUT];

    const int t    = threadIdx.x;
    const int wm   = t >> 5;
    const int l    = t & 31;
    const int base = blockIdx.x * M_BLK;

    if (t < COUT) { rsum[t] = 0.f; rsq[t] = 0.f; }

    const uint32_t sA_u = smem_u32(sA);
    const uint32_t sB_u = smem_u32(sB);
    const uint32_t a_base = sA_u + (uint32_t)((wm * 32 + (l & 15)) * APITCH
                                              + (l >> 4) * 16);
    const uint32_t b_base = sB_u + (uint32_t)(((l >> 4) * 8 + (l & 7)) * APITCH
                                              + ((l >> 3) & 1) * 16);

    float acc[2][8][4];
    #pragma unroll
    for (int mt = 0; mt < 2; ++mt)
        #pragma unroll
        for (int nt = 0; nt < 8; ++nt)
            #pragma unroll
            for (int j = 0; j < 4; ++j) acc[mt][nt][j] = 0.f;

    const int grow = t >> 3;        // 0..23
    const int gq   = t & 7;         // 16B chunk of the 128B packed row

    for (int k = 0; k < K_STENCIL; ++k) {
        __syncthreads();
        // ---- gather A: 192 packed rows (hi 64B + lo 64B), 8 thr/row ----
        #pragma unroll
        for (int p = 0; p < 8; ++p) {
            int row = p * 24 + grow;
            int n = base + row;
            int idx = (n < N) ? g_neigh_t[k * N + n] : -1;
            uint4 v = make_uint4(0, 0, 0, 0);
            if (idx >= 0)
                v = *(const uint4*)(g_data_pk + (size_t)idx * 64 + gq * 8);
            char* dst = (gq < 4) ? sA + row * APITCH + gq * 16
                                 : sA + A_LO + row * APITCH + (gq - 4) * 16;
            *(uint4*)dst = v;
        }
        // ---- load W_k: 64 packed rows, 512 16B chunks ----
        #pragma unroll
        for (int p = 0; p < 3; ++p) {
            int i = t + p * TPB;
            if (i < 512) {
                int half = i >> 8, rem = i & 255, n = rem >> 2, q = rem & 3;
                uint4 v = *(const uint4*)(g_w_pk + (k * COUT + n) * 64
                                          + half * 32 + q * 8);
                *(uint4*)(sB + half * B_LO + n * APITCH + q * 16) = v;
            }
        }
        __syncthreads();

        // ---- compute ----
        #pragma unroll
        for (int cs = 0; cs < 2; ++cs) {
            uint32_t ah[2][4], al[2][4];
            #pragma unroll
            for (int mt = 0; mt < 2; ++mt) {
                uint32_t aa = a_base + mt * (16 * APITCH) + cs * 32;
                LDMATRIX_X4(ah[mt][0], ah[mt][1], ah[mt][2], ah[mt][3], aa);
                LDMATRIX_X4(al[mt][0], al[mt][1], al[mt][2], al[mt][3], aa + A_LO);
            }
            #pragma unroll
            for (int ntp = 0; ntp < 4; ++ntp) {
                uint32_t bh0, bh1, bh2, bh3, bl0, bl1, bl2, bl3;
                uint32_t ba = b_base + ntp * (16 * APITCH) + cs * 32;
                LDMATRIX_X4(bh0, bh1, bh2, bh3, ba);
                LDMATRIX_X4(bl0, bl1, bl2, bl3, ba + B_LO);
                #pragma unroll
                for (int mt = 0; mt < 2; ++mt) {
                    MMA_BF16(acc[mt][2 * ntp],
                             ah[mt][0], ah[mt][1], ah[mt][2], ah[mt][3], bh0, bh1);
                    MMA_BF16(acc[mt][2 * ntp],
                             ah[mt][0], ah[mt][1], ah[mt][2], ah[mt][3], bl0, bl1);
                    MMA_BF16(acc[mt][2 * ntp],
                             al[mt][0], al[mt][1], al[mt][2], al[mt][3], bh0, bh1);
                    MMA_BF16(acc[mt][2 * ntp + 1],
                             ah[mt][0], ah[mt][1], ah[mt][2], ah[mt][3], bh2, bh3);
                    MMA_BF16(acc[mt][2 * ntp + 1],
                             ah[mt][0], ah[mt][1], ah[mt][2], ah[mt][3], bl2, bl3);
                    MMA_BF16(acc[mt][2 * ntp + 1],
                             al[mt][0], al[mt][1], al[mt][2], al[mt][3], bh2, bh3);
                }
            }
        }
    }

    // ---- epilogue: write out + BN partials ----
    #pragma unroll
    for (int mt = 0; mt < 2; ++mt) {
        const int r0 = base + wm * 32 + mt * 16 + (l >> 2);
        const int r1 = r0 + 8;
        #pragma unroll
        for (int nt = 0; nt < 8; ++nt) {
            float* a = acc[mt][nt];
            int c0 = nt * 8 + 2 * (l & 3);
            if (r0 < N)
                *(float2*)&out[(long long)r0 * COUT + c0] = make_float2(a[0], a[1]);
            if (r1 < N)
                *(float2*)&out[(long long)r1 * COUT + c0] = make_float2(a[2], a[3]);
            // rows >= N hold exact zeros (zero A rows) -> safe in sums
            float s0 = a[0] + a[2];
            float s1 = a[1] + a[3];
            float q0 = a[0] * a[0] + a[2] * a[2];
            float q1 = a[1] * a[1] + a[3] * a[3];
            #pragma unroll
            for (int m = 4; m < 32; m <<= 1) {
                s0 += __shfl_xor_sync(0xffffffffu, s0, m);
                s1 += __shfl_xor_sync(0xffffffffu, s1, m);
                q0 += __shfl_xor_sync(0xffffffffu, q0, m);
                q1 += __shfl_xor_sync(0xffffffffu, q1, m);
            }
            if (l < 4) {
                atomicAdd(&rsum[c0],     s0);
                atomicAdd(&rsum[c0 + 1], s1);
                atomicAdd(&rsq[c0],      q0);
                atomicAdd(&rsq[c0 + 1],  q1);
            }
        }
    }
    __syncthreads();
    if (t < COUT) {
        atomicAdd(&g_sum[t],   rsum[t]);
        atomicAdd(&g_sumsq[t], rsq[t]);
    }
}

__global__ void bn_finalize(const float* __restrict__ gamma,
                            const float* __restrict__ beta, float inv_n) {
    int o = threadIdx.x;
    if (o < COUT) {
        float mean = g_sum[o] * inv_n;
        float var  = g_sumsq[o] * inv_n - mean * mean;
        float s    = gamma[o] * rsqrtf(var + BN_EPS);
        g_scale[o] = s;
        g_bias[o]  = beta[o] - mean * s;
    }
}

__global__ void bn_apply(float* __restrict__ out, int total4) {
    int i      = blockIdx.x * blockDim.x + threadIdx.x;
    int stride = gridDim.x * blockDim.x;
    for (; i < total4; i += stride) {
        float4 v = ((float4*)out)[i];
        int o = (i & 15) * 4;
        float4 s = *(const float4*)&g_scale[o];
        float4 b = *(const float4*)&g_bias[o];
        v.x = fmaxf(fmaf(v.x, s.x, b.x), 0.f);
        v.y = fmaxf(fmaf(v.y, s.y, b.y), 0.f);
        v.z = fmaxf(fmaf(v.z, s.z, b.z), 0.f);
        v.w = fmaxf(fmaf(v.w, s.w, b.w), 0.f);
        ((float4*)out)[i] = v;
    }
}

extern "C" void kernel_launch(void* const* d_in, const int* in_sizes, int n_in,
                              void* d_out, int out_size) {
    const float* data   = (const float*)d_in[0];
    const void*  neigh  = d_in[1];
    const float* weight = (const float*)d_in[2];
    const float* gamma  = (const float*)d_in[3];
    const float* beta   = (const float*)d_in[4];
    float* out = (float*)d_out;

    int N = in_sizes[0] / CIN;

    prep_kernel<<<1, 128>>>((const int*)neigh, in_sizes[1]);

    int tot = N * K_STENCIL;
    tneigh_kernel<<<(tot + 255) / 256, 256>>>(neigh, N);

    int total4 = (N * CIN) / 4;
    cvt_data_kernel<<<2048, 256>>>(data, total4);
    cvt_weight_kernel<<<(K_STENCIL * COUT * CIN + 255) / 256, 256>>>(weight);

    int nblk = (N + M_BLK - 1) / M_BLK;
    conv_kernel<<<nblk, TPB>>>(out, N);

    bn_finalize<<<1, 64>>>(gamma, beta, 1.0f / (float)N);

    int out4 = (N * COUT) / 4;
    int blocks = (out4 + 511) / 512;
    if (blocks > 8192) blocks = 8192;
    bn_apply<<<blocks, 512>>>(out, out4);
}

// round 12
// speedup vs baseline: 1.0957x; 1.0957x over previous
#include <cuda_runtime.h>
#include <cuda_bf16.h>
#include <cstdint>

#define K_STENCIL 27
#define CIN 32
#define COUT 64
#define M_BLK 128
#define TPB 256
#define BN_EPS 1e-5f
#define MAX_N 320000

// smem row pitch: 64 data bytes + 16 pad -> ldmatrix/STS phases land on
// 8 distinct 16B banks (5*r mod 8 is a permutation of 0..7).
#define APITCH 80
#define A_LO (M_BLK * APITCH + 64)   // lo region offset (+64 = 4-bank shift)
#define B_LO (COUT * APITCH + 64)

// ---------------- device scratch (no allocation allowed) ----------------
__device__ int   g_is64;
__device__ float g_sum[COUT];
__device__ float g_sumsq[COUT];
__device__ float g_scale[COUT];
__device__ float g_bias[COUT];
// packed rows: 32 bf16 hi then 32 bf16 lo = 128 B per node / per (k,cout) row
__device__ __nv_bfloat16 g_data_pk[MAX_N * 64];
__device__ __nv_bfloat16 g_w_pk[K_STENCIL * COUT * 64];
__device__ int g_neigh_t[K_STENCIL * MAX_N];     // [k][node]

__device__ __forceinline__ uint32_t smem_u32(const void* p) {
    uint32_t a;
    asm("{ .reg .u64 t; cvta.to.shared.u64 t, %1; cvt.u32.u64 %0, t; }"
        : "=r"(a) : "l"(p));
    return a;
}

#define LDMATRIX_X4(r0, r1, r2, r3, addr) \
    asm volatile("ldmatrix.sync.aligned.m8n8.x4.shared.b16 {%0,%1,%2,%3}, [%4];" \
        : "=r"(r0), "=r"(r1), "=r"(r2), "=r"(r3) : "r"(addr))

#define MMA_BF16(d, a0, a1, a2, a3, b0, b1) \
    asm volatile("mma.sync.aligned.m16n8k16.row.col.f32.bf16.bf16.f32 " \
        "{%0,%1,%2,%3}, {%4,%5,%6,%7}, {%8,%9}, {%0,%1,%2,%3};" \
        : "+f"((d)[0]), "+f"((d)[1]), "+f"((d)[2]), "+f"((d)[3]) \
        : "r"(a0), "r"(a1), "r"(a2), "r"(a3), "r"(b0), "r"(b1))

// ---------------- small kernels ----------------
__global__ void prep_kernel(const int* __restrict__ neigh_words, int nelems) {
    int t = threadIdx.x;
    if (t < COUT) { g_sum[t] = 0.f; g_sumsq[t] = 0.f; }
    if (t >= 64 && t < 96) {
        int lane = t - 64;
        int v = 0;
        int limit = nelems < 4096 ? nelems : 4096;
        for (int i = 2 * lane + 1; i < limit; i += 64) v |= neigh_words[i];
        v = __reduce_or_sync(0xffffffffu, v);
        if (lane == 0) g_is64 = (v == 0) ? 1 : 0;
    }
}

// neigh [n][k] (int32 or int64) -> g_neigh_t [k][n] int32
__global__ void tneigh_kernel(const void* __restrict__ neigh, int N) {
    int i = blockIdx.x * blockDim.x + threadIdx.x;
    int total = N * K_STENCIL;
    if (i < total) {
        int n = i / K_STENCIL, k = i - n * K_STENCIL;
        long long idx = g_is64 ? ((const long long*)neigh)[i]
                               : (long long)((const int*)neigh)[i];
        g_neigh_t[k * N + n] = (idx >= 0) ? (int)idx : -1;
    }
}

__global__ void cvt_data_kernel(const float* __restrict__ data, int total4) {
    int i = blockIdx.x * blockDim.x + threadIdx.x;
    int stride = gridDim.x * blockDim.x;
    for (; i < total4; i += stride) {
        float4 x = ((const float4*)data)[i];
        int n = i >> 3, c = (i & 7) * 4;
        __nv_bfloat16 h0 = __float2bfloat16_rn(x.x);
        __nv_bfloat16 h1 = __float2bfloat16_rn(x.y);
        __nv_bfloat16 h2 = __float2bfloat16_rn(x.z);
        __nv_bfloat16 h3 = __float2bfloat16_rn(x.w);
        __nv_bfloat16 l0 = __float2bfloat16_rn(x.x - __bfloat162float(h0));
        __nv_bfloat16 l1 = __float2bfloat16_rn(x.y - __bfloat162float(h1));
        __nv_bfloat16 l2 = __float2bfloat16_rn(x.z - __bfloat162float(h2));
        __nv_bfloat16 l3 = __float2bfloat16_rn(x.w - __bfloat162float(h3));
        uint2 hp, lp;
        hp.x = ((uint32_t)__bfloat16_as_ushort(h1) << 16) | __bfloat16_as_ushort(h0);
        hp.y = ((uint32_t)__bfloat16_as_ushort(h3) << 16) | __bfloat16_as_ushort(h2);
        lp.x = ((uint32_t)__bfloat16_as_ushort(l1) << 16) | __bfloat16_as_ushort(l0);
        lp.y = ((uint32_t)__bfloat16_as_ushort(l3) << 16) | __bfloat16_as_ushort(l2);
        *(uint2*)&g_data_pk[n * 64 + c]      = hp;
        *(uint2*)&g_data_pk[n * 64 + 32 + c] = lp;
    }
}

__global__ void cvt_weight_kernel(const float* __restrict__ weight) {
    int i = blockIdx.x * blockDim.x + threadIdx.x;
    int total = K_STENCIL * COUT * CIN;
    if (i < total) {
        int k = i / (COUT * CIN);
        int r = i - k * (COUT * CIN);
        int n = r >> 5;            // cout
        int c = r & 31;            // cin
        float x = weight[(k * CIN + c) * COUT + n];
        __nv_bfloat16 h = __float2bfloat16_rn(x);
        __nv_bfloat16 l = __float2bfloat16_rn(x - __bfloat162float(h));
        g_w_pk[(k * COUT + n) * 64 + c]      = h;
        g_w_pk[(k * COUT + n) * 64 + 32 + c] = l;
    }
}

// ---------------- main conv kernel: warp-level bf16 HMMA, hi/lo split ----
// Block: 128 nodes x 64 couts, 8 warps in a 4x2 grid:
//   wmq = w&3 -> node quarter  [wmq*32, wmq*32+32)  (two m16 tiles)
//   wn  = w>>2 -> cout half    [wn*32, wn*32+32)    (two n16 tile pairs)
// Each warp: 32 accs, 48 MMA / k. B fragments amortize over 32 nodes,
// A fragments over 32 couts -> LDSM bytes/node = 256 (vs 640 in R9).
__global__ void __launch_bounds__(TPB, 3) conv_kernel(float* __restrict__ out, int N)
{
    __shared__ __align__(128) char sA[2 * M_BLK * APITCH + 64];  // hi | pad | lo
    __shared__ __align__(128) char sB[2 * COUT * APITCH + 64];
    __shared__ float rsum[COUT], rsq[COUT];

    const int t    = threadIdx.x;
    const int w    = t >> 5;
    const int l    = t & 31;
    const int wmq  = w & 3;
    const int wn   = w >> 2;
    const int base = blockIdx.x * M_BLK;

    if (t < COUT) { rsum[t] = 0.f; rsq[t] = 0.f; }

    const uint32_t sA_u = smem_u32(sA);
    const uint32_t sB_u = smem_u32(sB);
    const uint32_t a_base = sA_u + (uint32_t)((wmq * 32 + (l & 15)) * APITCH
                                              + (l >> 4) * 16);
    const uint32_t b_base = sB_u + (uint32_t)((wn * 32 + (l >> 4) * 8 + (l & 7)) * APITCH
                                              + ((l >> 3) & 1) * 16);

    float acc[2][4][4];
    #pragma unroll
    for (int mt = 0; mt < 2; ++mt)
        #pragma unroll
        for (int nt = 0; nt < 4; ++nt)
            #pragma unroll
            for (int j = 0; j < 4; ++j) acc[mt][nt][j] = 0.f;

    const int grow = t >> 3;        // 0..31 (row within pass)
    const int gq   = t & 7;         // 16B chunk of the 128B packed row

    for (int k = 0; k < K_STENCIL; ++k) {
        __syncthreads();
        // ---- gather A: 128 packed rows (hi 64B | lo 64B), 8 thr/row ----
        #pragma unroll
        for (int p = 0; p < 4; ++p) {
            int row = p * 32 + grow;
            int n = base + row;
            int idx = (n < N) ? g_neigh_t[k * N + n] : -1;
            uint4 v = make_uint4(0, 0, 0, 0);
            if (idx >= 0)
                v = *(const uint4*)(g_data_pk + (size_t)idx * 64 + gq * 8);
            char* dst = (gq < 4) ? sA + row * APITCH + gq * 16
                                 : sA + A_LO + row * APITCH + (gq - 4) * 16;
            *(uint4*)dst = v;
        }
        // ---- load W_k: 64 packed rows = 512 16B chunks, 2/thread ----
        #pragma unroll
        for (int p = 0; p < 2; ++p) {
            int i = t + p * TPB;
            int half = i >> 8, rem = i & 255, n = rem >> 2, q = rem & 3;
            uint4 v = *(const uint4*)(g_w_pk + (k * COUT + n) * 64
                                      + half * 32 + q * 8);
            *(uint4*)(sB + half * B_LO + n * APITCH + q * 16) = v;
        }
        __syncthreads();

        // ---- compute: 2 cs x (2 A-tiles, 2 B-tile-pairs) x 3 combos ----
        #pragma unroll
        for (int cs = 0; cs < 2; ++cs) {
            uint32_t ah[2][4], al[2][4];
            #pragma unroll
            for (int mt = 0; mt < 2; ++mt) {
                uint32_t aa = a_base + mt * (16 * APITCH) + cs * 32;
                LDMATRIX_X4(ah[mt][0], ah[mt][1], ah[mt][2], ah[mt][3], aa);
                LDMATRIX_X4(al[mt][0], al[mt][1], al[mt][2], al[mt][3], aa + A_LO);
            }
            #pragma unroll
            for (int ntp = 0; ntp < 2; ++ntp) {
                uint32_t bh0, bh1, bh2, bh3, bl0, bl1, bl2, bl3;
                uint32_t ba = b_base + ntp * (16 * APITCH) + cs * 32;
                LDMATRIX_X4(bh0, bh1, bh2, bh3, ba);
                LDMATRIX_X4(bl0, bl1, bl2, bl3, ba + B_LO);
                #pragma unroll
                for (int mt = 0; mt < 2; ++mt) {
                    MMA_BF16(acc[mt][2 * ntp],
                             ah[mt][0], ah[mt][1], ah[mt][2], ah[mt][3], bh0, bh1);
                    MMA_BF16(acc[mt][2 * ntp],
                             ah[mt][0], ah[mt][1], ah[mt][2], ah[mt][3], bl0, bl1);
                    MMA_BF16(acc[mt][2 * ntp],
                             al[mt][0], al[mt][1], al[mt][2], al[mt][3], bh0, bh1);
                    MMA_BF16(acc[mt][2 * ntp + 1],
                             ah[mt][0], ah[mt][1], ah[mt][2], ah[mt][3], bh2, bh3);
                    MMA_BF16(acc[mt][2 * ntp + 1],
                             ah[mt][0], ah[mt][1], ah[mt][2], ah[mt][3], bl2, bl3);
                    MMA_BF16(acc[mt][2 * ntp + 1],
                             al[mt][0], al[mt][1], al[mt][2], al[mt][3], bh2, bh3);
                }
            }
        }
    }

    // ---- epilogue: write out + BN partials ----
    #pragma unroll
    for (int mt = 0; mt < 2; ++mt) {
        const int r0 = base + wmq * 32 + mt * 16 + (l >> 2);
        const int r1 = r0 + 8;
        #pragma unroll
        for (int nt = 0; nt < 4; ++nt) {
            float* a = acc[mt][nt];
            int c0 = wn * 32 + nt * 8 + 2 * (l & 3);
            if (r0 < N)
                *(float2*)&out[(long long)r0 * COUT + c0] = make_float2(a[0], a[1]);
            if (r1 < N)
                *(float2*)&out[(long long)r1 * COUT + c0] = make_float2(a[2], a[3]);
            // rows >= N hold exact zeros (zero A rows) -> safe in sums
            float s0 = a[0] + a[2];
            float s1 = a[1] + a[3];
            float q0 = a[0] * a[0] + a[2] * a[2];
            float q1 = a[1] * a[1] + a[3] * a[3];
            #pragma unroll
            for (int m = 4; m < 32; m <<= 1) {
                s0 += __shfl_xor_sync(0xffffffffu, s0, m);
                s1 += __shfl_xor_sync(0xffffffffu, s1, m);
                q0 += __shfl_xor_sync(0xffffffffu, q0, m);
                q1 += __shfl_xor_sync(0xffffffffu, q1, m);
            }
            if (l < 4) {
                atomicAdd(&rsum[c0],     s0);
                atomicAdd(&rsum[c0 + 1], s1);
                atomicAdd(&rsq[c0],      q0);
                atomicAdd(&rsq[c0 + 1],  q1);
            }
        }
    }
    __syncthreads();
    if (t < COUT) {
        atomicAdd(&g_sum[t],   rsum[t]);
        atomicAdd(&g_sumsq[t], rsq[t]);
    }
}

__global__ void bn_finalize(const float* __restrict__ gamma,
                            const float* __restrict__ beta, float inv_n) {
    int o = threadIdx.x;
    if (o < COUT) {
        float mean = g_sum[o] * inv_n;
        float var  = g_sumsq[o] * inv_n - mean * mean;
        float s    = gamma[o] * rsqrtf(var + BN_EPS);
        g_scale[o] = s;
        g_bias[o]  = beta[o] - mean * s;
    }
}

__global__ void bn_apply(float* __restrict__ out, int total4) {
    int i      = blockIdx.x * blockDim.x + threadIdx.x;
    int stride = gridDim.x * blockDim.x;
    for (; i < total4; i += stride) {
        float4 v = ((float4*)out)[i];
        int o = (i & 15) * 4;
        float4 s = *(const float4*)&g_scale[o];
        float4 b = *(const float4*)&g_bias[o];
        v.x = fmaxf(fmaf(v.x, s.x, b.x), 0.f);
        v.y = fmaxf(fmaf(v.y, s.y, b.y), 0.f);
        v.z = fmaxf(fmaf(v.z, s.z, b.z), 0.f);
        v.w = fmaxf(fmaf(v.w, s.w, b.w), 0.f);
        ((float4*)out)[i] = v;
    }
}

extern "C" void kernel_launch(void* const* d_in, const int* in_sizes, int n_in,
                              void* d_out, int out_size) {
    const float* data   = (const float*)d_in[0];
    const void*  neigh  = d_in[1];
    const float* weight = (const float*)d_in[2];
    const float* gamma  = (const float*)d_in[3];
    const float* beta   = (const float*)d_in[4];
    float* out = (float*)d_out;

    int N = in_sizes[0] / CIN;

    prep_kernel<<<1, 128>>>((const int*)neigh, in_sizes[1]);

    int tot = N * K_STENCIL;
    tneigh_kernel<<<(tot + 255) / 256, 256>>>(neigh, N);

    int total4 = (N * CIN) / 4;
    cvt_data_kernel<<<2048, 256>>>(data, total4);
    cvt_weight_kernel<<<(K_STENCIL * COUT * CIN + 255) / 256, 256>>>(weight);

    int nblk = (N + M_BLK - 1) / M_BLK;
    conv_kernel<<<nblk, TPB>>>(out, N);

    bn_finalize<<<1, 64>>>(gamma, beta, 1.0f / (float)N);

    int out4 = (N * COUT) / 4;
    int blocks = (out4 + 511) / 512;
    if (blocks > 8192) blocks = 8192;
    bn_apply<<<blocks, 512>>>(out, out4);
}

// round 13
// speedup vs baseline: 2.1158x; 1.9310x over previous
#include <cuda_runtime.h>
#include <cuda_bf16.h>
#include <cstdint>

#define K_STENCIL 27
#define CIN 32
#define COUT 64
#define M_BLK 128
#define TPB 256
#define BN_EPS 1e-5f
#define MAX_N 320000

// smem row pitch: 64 data bytes + 16 pad -> ldmatrix phase addresses land on
// 8 distinct 16B banks (5*r mod 8 is a permutation of 0..7).
#define APITCH 80

// ---------------- device scratch (no allocation allowed) ----------------
__device__ int   g_is64;
__device__ float g_sum[COUT];
__device__ float g_sumsq[COUT];
__device__ float g_scale[COUT];
__device__ float g_bias[COUT];
__device__ __nv_bfloat16 g_data_hi[MAX_N * CIN];
__device__ __nv_bfloat16 g_data_lo[MAX_N * CIN];
__device__ __nv_bfloat16 g_w_hi[K_STENCIL * COUT * CIN];   // [k][cout][cin]
__device__ __nv_bfloat16 g_w_lo[K_STENCIL * COUT * CIN];

__device__ __forceinline__ uint32_t smem_u32(const void* p) {
    uint32_t a;
    asm("{ .reg .u64 t; cvta.to.shared.u64 t, %1; cvt.u32.u64 %0, t; }"
        : "=r"(a) : "l"(p));
    return a;
}

#define LDMATRIX_X4(r0, r1, r2, r3, addr) \
    asm volatile("ldmatrix.sync.aligned.m8n8.x4.shared.b16 {%0,%1,%2,%3}, [%4];" \
        : "=r"(r0), "=r"(r1), "=r"(r2), "=r"(r3) : "r"(addr))

#define MMA_BF16(d, a0, a1, a2, a3, b0, b1) \
    asm volatile("mma.sync.aligned.m16n8k16.row.col.f32.bf16.bf16.f32 " \
        "{%0,%1,%2,%3}, {%4,%5,%6,%7}, {%8,%9}, {%0,%1,%2,%3};" \
        : "+f"((d)[0]), "+f"((d)[1]), "+f"((d)[2]), "+f"((d)[3]) \
        : "r"(a0), "r"(a1), "r"(a2), "r"(a3), "r"(b0), "r"(b1))

// ---------------- small kernels ----------------
__global__ void prep_kernel(const int* __restrict__ neigh_words, int nelems) {
    int t = threadIdx.x;
    if (t < COUT) { g_sum[t] = 0.f; g_sumsq[t] = 0.f; }
    if (t >= 64 && t < 96) {
        int lane = t - 64;
        int v = 0;
        int limit = nelems < 4096 ? nelems : 4096;
        for (int i = 2 * lane + 1; i < limit; i += 64) v |= neigh_words[i];
        v = __reduce_or_sync(0xffffffffu, v);
        if (lane == 0) g_is64 = (v == 0) ? 1 : 0;
    }
}

__global__ void cvt_data_kernel(const float* __restrict__ data, int total4) {
    int i = blockIdx.x * blockDim.x + threadIdx.x;
    int stride = gridDim.x * blockDim.x;
    for (; i < total4; i += stride) {
        float4 x = ((const float4*)data)[i];
        __nv_bfloat16 h0 = __float2bfloat16_rn(x.x);
        __nv_bfloat16 h1 = __float2bfloat16_rn(x.y);
        __nv_bfloat16 h2 = __float2bfloat16_rn(x.z);
        __nv_bfloat16 h3 = __float2bfloat16_rn(x.w);
        __nv_bfloat16 l0 = __float2bfloat16_rn(x.x - __bfloat162float(h0));
        __nv_bfloat16 l1 = __float2bfloat16_rn(x.y - __bfloat162float(h1));
        __nv_bfloat16 l2 = __float2bfloat16_rn(x.z - __bfloat162float(h2));
        __nv_bfloat16 l3 = __float2bfloat16_rn(x.w - __bfloat162float(h3));
        uint2 hp, lp;
        hp.x = ((uint32_t)__bfloat16_as_ushort(h1) << 16) | __bfloat16_as_ushort(h0);
        hp.y = ((uint32_t)__bfloat16_as_ushort(h3) << 16) | __bfloat16_as_ushort(h2);
        lp.x = ((uint32_t)__bfloat16_as_ushort(l1) << 16) | __bfloat16_as_ushort(l0);
        lp.y = ((uint32_t)__bfloat16_as_ushort(l3) << 16) | __bfloat16_as_ushort(l2);
        *(uint2*)&g_data_hi[i * 4] = hp;
        *(uint2*)&g_data_lo[i * 4] = lp;
    }
}

__global__ void cvt_weight_kernel(const float* __restrict__ weight) {
    int i = blockIdx.x * blockDim.x + threadIdx.x;
    int total = K_STENCIL * COUT * CIN;
    if (i < total) {
        int k = i / (COUT * CIN);
        int r = i - k * (COUT * CIN);
        int n = r >> 5;            // cout
        int c = r & 31;            // cin
        float x = weight[(k * CIN + c) * COUT + n];
        __nv_bfloat16 h = __float2bfloat16_rn(x);
        __nv_bfloat16 l = __float2bfloat16_rn(x - __bfloat162float(h));
        g_w_hi[i] = h;
        g_w_lo[i] = l;
    }
}

// ---------------- main conv kernel: warp-level bf16 HMMA, hi/lo split ----
// Identical to the 491us kernel EXCEPT the warp tiling: 8 warps in a 4x2 grid
//   wmq = w&3 -> node quarter [wmq*32, wmq*32+32)  (two m16 tiles)
//   wn  = w>>2 -> cout half   [wn*32, wn*32+32)    (two n16 tile pairs)
// Each warp: 32 accs, 16 LDSM.x4 + 48 MMA per k (was 20 LDSM.x4 + 48 MMA).
__global__ void __launch_bounds__(TPB, 3) conv_kernel(
    const void* __restrict__ neigh, float* __restrict__ out, int N)
{
    __shared__ __align__(16) char sA[2 * M_BLK * APITCH];   // hi, lo (20.0 KB)
    __shared__ __align__(16) char sB[2 * COUT * APITCH];    // hi, lo (10.0 KB)
    __shared__ int   sidx[K_STENCIL * M_BLK];               // 13.5 KB
    __shared__ float rsum[COUT], rsq[COUT];

    const int t    = threadIdx.x;
    const int w    = t >> 5;
    const int l    = t & 31;
    const int wmq  = w & 3;
    const int wn   = w >> 2;
    const int base = blockIdx.x * M_BLK;

    if (t < COUT) { rsum[t] = 0.f; rsq[t] = 0.f; }

    // Preload all neighbor indices, [k][node] layout (dtype-dispatched).
    if (g_is64) {
        const long long* nn = (const long long*)neigh;
        for (int i = t; i < K_STENCIL * M_BLK; i += TPB) {
            int k = i >> 7, node = i & 127;
            int n = base + node;
            sidx[i] = (n < N) ? (int)nn[(long long)n * K_STENCIL + k] : -1;
        }
    } else {
        const int* nn = (const int*)neigh;
        for (int i = t; i < K_STENCIL * M_BLK; i += TPB) {
            int k = i >> 7, node = i & 127;
            int n = base + node;
            sidx[i] = (n < N) ? nn[n * K_STENCIL + k] : -1;
        }
    }

    const uint32_t sA_u = smem_u32(sA);
    const uint32_t sB_u = smem_u32(sB);
    // ldmatrix lane address offsets (row part), computed once.
    const uint32_t a_base = sA_u + (uint32_t)((wmq * 32 + (l & 15)) * APITCH
                                              + ((l >> 4) & 1) * 16);
    const uint32_t b_base = sB_u + (uint32_t)((wn * 32 + (l >> 4) * 8 + (l & 7)) * APITCH
                                              + ((l >> 3) & 1) * 16);

    float acc[2][4][4];
    #pragma unroll
    for (int mt = 0; mt < 2; ++mt)
        #pragma unroll
        for (int nt = 0; nt < 4; ++nt)
            #pragma unroll
            for (int j = 0; j < 4; ++j) acc[mt][nt][j] = 0.f;

    const int gnode = t >> 1;       // gather: row per thread pair
    const int ghalf = t & 1;        // 32B half of the 64B row

    for (int k = 0; k < K_STENCIL; ++k) {
        __syncthreads();
        // ---- gather A (hi+lo): 128 rows x 64 B each ----
        {
            int idx = sidx[k * M_BLK + gnode];
            uint4 h0, h1, l0, l1;
            if (idx >= 0) {
                const uint4* ph = (const uint4*)(g_data_hi + (long long)idx * CIN)
                                  + ghalf * 2;
                const uint4* pl = (const uint4*)(g_data_lo + (long long)idx * CIN)
                                  + ghalf * 2;
                h0 = ph[0]; h1 = ph[1];
                l0 = pl[0]; l1 = pl[1];
            } else {
                h0 = h1 = l0 = l1 = make_uint4(0, 0, 0, 0);
            }
            char* pa = sA + gnode * APITCH + ghalf * 32;
            *(uint4*)(pa)      = h0;
            *(uint4*)(pa + 16) = h1;
            *(uint4*)(pa + M_BLK * APITCH)      = l0;
            *(uint4*)(pa + M_BLK * APITCH + 16) = l1;
        }
        // ---- load W_k (hi+lo): 64 rows x 64 B each ----
        {
            int n = t >> 2, q = t & 3;               // 256 thr = 64 rows x 4 chunks
            const uint4* wh = (const uint4*)(g_w_hi + (k * COUT + n) * CIN) + q;
            const uint4* wl = (const uint4*)(g_w_lo + (k * COUT + n) * CIN) + q;
            char* pb = sB + n * APITCH + q * 16;
            *(uint4*)pb = *wh;
            *(uint4*)(pb + COUT * APITCH) = *wl;
        }
        __syncthreads();

        // ---- compute: 2 cs x (2 A-tiles x 2 B-tile-pairs) x 3 combos ----
        #pragma unroll
        for (int cs = 0; cs < 2; ++cs) {
            uint32_t ah[2][4], al[2][4];
            #pragma unroll
            for (int mt = 0; mt < 2; ++mt) {
                uint32_t aa = a_base + mt * (16 * APITCH) + cs * 32;
                LDMATRIX_X4(ah[mt][0], ah[mt][1], ah[mt][2], ah[mt][3], aa);
                LDMATRIX_X4(al[mt][0], al[mt][1], al[mt][2], al[mt][3],
                            aa + M_BLK * APITCH);
            }
            #pragma unroll
            for (int ntp = 0; ntp < 2; ++ntp) {
                uint32_t bh0, bh1, bh2, bh3, bl0, bl1, bl2, bl3;
                uint32_t ba = b_base + ntp * (16 * APITCH) + cs * 32;
                LDMATRIX_X4(bh0, bh1, bh2, bh3, ba);
                LDMATRIX_X4(bl0, bl1, bl2, bl3, ba + COUT * APITCH);
                #pragma unroll
                for (int mt = 0; mt < 2; ++mt) {
                    MMA_BF16(acc[mt][2 * ntp],
                             ah[mt][0], ah[mt][1], ah[mt][2], ah[mt][3], bh0, bh1);
                    MMA_BF16(acc[mt][2 * ntp],
                             ah[mt][0], ah[mt][1], ah[mt][2], ah[mt][3], bl0, bl1);
                    MMA_BF16(acc[mt][2 * ntp],
                             al[mt][0], al[mt][1], al[mt][2], al[mt][3], bh0, bh1);
                    MMA_BF16(acc[mt][2 * ntp + 1],
                             ah[mt][0], ah[mt][1], ah[mt][2], ah[mt][3], bh2, bh3);
                    MMA_BF16(acc[mt][2 * ntp + 1],
                             ah[mt][0], ah[mt][1], ah[mt][2], ah[mt][3], bl2, bl3);
                    MMA_BF16(acc[mt][2 * ntp + 1],
                             al[mt][0], al[mt][1], al[mt][2], al[mt][3], bh2, bh3);
                }
            }
        }
    }

    // ---- epilogue: write out + BN partials ----
    #pragma unroll
    for (int mt = 0; mt < 2; ++mt) {
        const int r0 = base + wmq * 32 + mt * 16 + (l >> 2);
        const int r1 = r0 + 8;
        #pragma unroll
        for (int nt = 0; nt < 4; ++nt) {
            float* a = acc[mt][nt];
            int c0 = wn * 32 + nt * 8 + 2 * (l & 3);
            if (r0 < N)
                *(float2*)&out[(long long)r0 * COUT + c0] = make_float2(a[0], a[1]);
            if (r1 < N)
                *(float2*)&out[(long long)r1 * COUT + c0] = make_float2(a[2], a[3]);
            // rows >= N hold exact zeros (zero A rows) -> safe in sums
            float s0 = a[0] + a[2];
            float s1 = a[1] + a[3];
            float q0 = a[0] * a[0] + a[2] * a[2];
            float q1 = a[1] * a[1] + a[3] * a[3];
            #pragma unroll
            for (int m = 4; m < 32; m <<= 1) {
                s0 += __shfl_xor_sync(0xffffffffu, s0, m);
                s1 += __shfl_xor_sync(0xffffffffu, s1, m);
                q0 += __shfl_xor_sync(0xffffffffu, q0, m);
                q1 += __shfl_xor_sync(0xffffffffu, q1, m);
            }
            if (l < 4) {
                atomicAdd(&rsum[c0],     s0);
                atomicAdd(&rsum[c0 + 1], s1);
                atomicAdd(&rsq[c0],      q0);
                atomicAdd(&rsq[c0 + 1],  q1);
            }
        }
    }
    __syncthreads();
    if (t < COUT) {
        atomicAdd(&g_sum[t],   rsum[t]);
        atomicAdd(&g_sumsq[t], rsq[t]);
    }
}

__global__ void bn_finalize(const float* __restrict__ gamma,
                            const float* __restrict__ beta, float inv_n) {
    int o = threadIdx.x;
    if (o < COUT) {
        float mean = g_sum[o] * inv_n;
        float var  = g_sumsq[o] * inv_n - mean * mean;
        float s    = gamma[o] * rsqrtf(var + BN_EPS);
        g_scale[o] = s;
        g_bias[o]  = beta[o] - mean * s;
    }
}

__global__ void bn_apply(float* __restrict__ out, int total4) {
    int i      = blockIdx.x * blockDim.x + threadIdx.x;
    int stride = gridDim.x * blockDim.x;
    for (; i < total4; i += stride) {
        float4 v = ((float4*)out)[i];
        int o = (i & 15) * 4;
        float4 s = *(const float4*)&g_scale[o];
        float4 b = *(const float4*)&g_bias[o];
        v.x = fmaxf(fmaf(v.x, s.x, b.x), 0.f);
        v.y = fmaxf(fmaf(v.y, s.y, b.y), 0.f);
        v.z = fmaxf(fmaf(v.z, s.z, b.z), 0.f);
        v.w = fmaxf(fmaf(v.w, s.w, b.w), 0.f);
        ((float4*)out)[i] = v;
    }
}

extern "C" void kernel_launch(void* const* d_in, const int* in_sizes, int n_in,
                              void* d_out, int out_size) {
    const float* data   = (const float*)d_in[0];
    const void*  neigh  = d_in[1];
    const float* weight = (const float*)d_in[2];
    const float* gamma  = (const float*)d_in[3];
    const float* beta   = (const float*)d_in[4];
    float* out = (float*)d_out;

    int N = in_sizes[0] / CIN;

    prep_kernel<<<1, 128>>>((const int*)neigh, in_sizes[1]);

    int total4 = (N * CIN) / 4;
    cvt_data_kernel<<<2048, 256>>>(data, total4);
    cvt_weight_kernel<<<(K_STENCIL * COUT * CIN + 255) / 256, 256>>>(weight);

    int nblk = (N + M_BLK - 1) / M_BLK;
    conv_kernel<<<nblk, TPB>>>(neigh, out, N);

    bn_finalize<<<1, 64>>>(gamma, beta, 1.0f / (float)N);

    int out4 = (N * COUT) / 4;
    int blocks = (out4 + 511) / 512;
    if (blocks > 8192) blocks = 8192;
    bn_apply<<<blocks, 512>>>(out, out4);
}